// round 3
// baseline (speedup 1.0000x reference)
#include <cuda_runtime.h>
#include <cuda_bf16.h>
#include <cstdint>

#define N_NODES 100000
#define IN_DIM  256
#define OUT_DIM 128
#define ALPHA   0.1f
#define EPS     9e-15f

// ---------------- scratch (device globals; no runtime allocation) ----------
__device__ __align__(16) float g_h[(size_t)N_NODES * OUT_DIM];        // 51.2 MB
__device__ __align__(16) float g_hprime[(size_t)N_NODES * OUT_DIM];   // 51.2 MB
__device__ __align__(16) float g_score_l[N_NODES];
__device__ __align__(16) float g_score_r[N_NODES];
__device__ __align__(16) float g_rowsum[N_NODES];
__device__ int g_is64;   // 1 if edge_index buffer is genuinely int64

// ---------------------------------------------------------------------------
// Kernel 0: zero accumulators + reset dtype flag
// ---------------------------------------------------------------------------
__global__ void zero_kernel() {
    int i = blockIdx.x * blockDim.x + threadIdx.x;
    const int tot4 = N_NODES * (OUT_DIM / 4);   // 3.2M float4
    if (i < tot4) {
        ((float4*)g_hprime)[i] = make_float4(0.f, 0.f, 0.f, 0.f);
    }
    if (i < N_NODES) g_rowsum[i] = 0.f;
    if (i == 0) g_is64 = 1;
}

// ---------------------------------------------------------------------------
// Kernel 0b: probe edge_index dtype.
// Interpret first K entries as int64; if ANY falls outside [0, N_NODES),
// the buffer is int32 (pairs fused into bogus 64-bit values).
// ---------------------------------------------------------------------------
__global__ void probe_kernel(const void* ei, int n_elems64) {
    const long long* p = (const long long*)ei;
    int i = threadIdx.x + blockIdx.x * blockDim.x;
    int K = n_elems64 < 4096 ? n_elems64 : 4096;
    if (i < K) {
        long long v = p[i];
        if (v < 0 || v >= N_NODES) atomicAnd(&g_is64, 0);
    }
}

// ---------------------------------------------------------------------------
// Kernel 1: SGEMM  H[M,128] = X[M,256] @ W[256,128]
// 128x128 block tile, BK=8, 256 threads, 8x8 per-thread microtile
// ---------------------------------------------------------------------------
__global__ __launch_bounds__(256) void gemm_kernel(const float* __restrict__ X,
                                                   const float* __restrict__ W) {
    __shared__ float As[8][128];   // [k][m]
    __shared__ float Bs[8][128];   // [k][n]

    const int block_row = blockIdx.x * 128;
    const int tid = threadIdx.x;
    const int ty = tid >> 4;          // 0..15  (m-tile)
    const int tx = tid & 15;          // 0..15  (n-tile)

    const int arow = tid >> 1;            // 0..127
    const int acol = (tid & 1) * 4;       // 0 or 4
    const int brow = tid >> 5;            // 0..7
    const int bcol = (tid & 31) * 4;      // 0..124

    float acc[8][8];
    #pragma unroll
    for (int i = 0; i < 8; i++)
        #pragma unroll
        for (int j = 0; j < 8; j++) acc[i][j] = 0.f;

    const int gr = block_row + arow;

    for (int kt = 0; kt < IN_DIM; kt += 8) {
        float4 av = make_float4(0.f, 0.f, 0.f, 0.f);
        if (gr < N_NODES)
            av = *(const float4*)(X + (size_t)gr * IN_DIM + kt + acol);
        As[acol + 0][arow] = av.x;
        As[acol + 1][arow] = av.y;
        As[acol + 2][arow] = av.z;
        As[acol + 3][arow] = av.w;

        float4 bv = *(const float4*)(W + (size_t)(kt + brow) * OUT_DIM + bcol);
        *(float4*)&Bs[brow][bcol] = bv;

        __syncthreads();

        #pragma unroll
        for (int k = 0; k < 8; k++) {
            float ar[8], br[8];
            *(float4*)&ar[0] = *(float4*)&As[k][ty * 8];
            *(float4*)&ar[4] = *(float4*)&As[k][ty * 8 + 4];
            *(float4*)&br[0] = *(float4*)&Bs[k][tx * 8];
            *(float4*)&br[4] = *(float4*)&Bs[k][tx * 8 + 4];
            #pragma unroll
            for (int i = 0; i < 8; i++)
                #pragma unroll
                for (int j = 0; j < 8; j++)
                    acc[i][j] += ar[i] * br[j];
        }
        __syncthreads();
    }

    #pragma unroll
    for (int i = 0; i < 8; i++) {
        const int row = block_row + ty * 8 + i;
        if (row < N_NODES) {
            float* hp = g_h + (size_t)row * OUT_DIM + tx * 8;
            *(float4*)(hp)     = *(float4*)&acc[i][0];
            *(float4*)(hp + 4) = *(float4*)&acc[i][4];
        }
    }
}

// ---------------------------------------------------------------------------
// Kernel 2: per-node attention scores  (one warp per node)
// ---------------------------------------------------------------------------
__global__ __launch_bounds__(256) void score_kernel(const float* __restrict__ attn) {
    const int warp = (blockIdx.x * blockDim.x + threadIdx.x) >> 5;
    const int lane = threadIdx.x & 31;
    if (warp >= N_NODES) return;

    float4 hv = *(const float4*)(g_h + (size_t)warp * OUT_DIM + lane * 4);
    float4 al = *(const float4*)(attn + lane * 4);
    float4 ar = *(const float4*)(attn + OUT_DIM + lane * 4);

    float dl = hv.x * al.x + hv.y * al.y + hv.z * al.z + hv.w * al.w;
    float dr = hv.x * ar.x + hv.y * ar.y + hv.z * ar.z + hv.w * ar.w;

    #pragma unroll
    for (int off = 16; off > 0; off >>= 1) {
        dl += __shfl_xor_sync(0xffffffff, dl, off);
        dr += __shfl_xor_sync(0xffffffff, dr, off);
    }
    if (lane == 0) {
        g_score_l[warp] = dl;
        g_score_r[warp] = dr;
    }
}

// ---------------------------------------------------------------------------
// Kernel 3: edge aggregation  (one warp per edge)
//   w = exp(leaky_relu(score_l[src] + score_r[dst]))
//   hprime[src] += w * h[dst]   (float4 atomicAdd -> RED.E.ADD.V4)
//   rowsum[src] += w
// ---------------------------------------------------------------------------
__global__ __launch_bounds__(256) void edge_kernel(const void* __restrict__ ei_raw,
                                                   const int n_edges) {
    const int warp = (blockIdx.x * blockDim.x + threadIdx.x) >> 5;
    const int lane = threadIdx.x & 31;
    if (warp >= n_edges) return;

    int src, dst;
    if (g_is64) {
        const long long* ei = (const long long*)ei_raw;
        src = (int)ei[warp];
        dst = (int)ei[(size_t)n_edges + warp];
    } else {
        const int* ei = (const int*)ei_raw;
        src = ei[warp];
        dst = ei[(size_t)n_edges + warp];
    }
    if ((unsigned)src >= N_NODES || (unsigned)dst >= N_NODES) return;

    float s = g_score_l[src] + g_score_r[dst];
    s = (s > 0.f) ? s : ALPHA * s;
    const float w = __expf(s);

    float4 v = *(const float4*)(g_h + (size_t)dst * OUT_DIM + lane * 4);
    float4* outp = (float4*)(g_hprime + (size_t)src * OUT_DIM + lane * 4);
    atomicAdd(outp, make_float4(w * v.x, w * v.y, w * v.z, w * v.w));

    if (lane == 0) atomicAdd(&g_rowsum[src], w);
}

// ---------------------------------------------------------------------------
// Kernel 4: finalize  out = leaky_relu(hprime / (rowsum + EPS))
// ---------------------------------------------------------------------------
__global__ __launch_bounds__(256) void finalize_kernel(float* __restrict__ out) {
    const int i = blockIdx.x * blockDim.x + threadIdx.x;   // float4 index
    const int tot4 = N_NODES * (OUT_DIM / 4);
    if (i >= tot4) return;
    const int node = i >> 5;   // 32 float4 per node
    const float inv = 1.0f / (g_rowsum[node] + EPS);
    float4 v = ((const float4*)g_hprime)[i];
    v.x *= inv; v.y *= inv; v.z *= inv; v.w *= inv;
    v.x = (v.x > 0.f) ? v.x : ALPHA * v.x;
    v.y = (v.y > 0.f) ? v.y : ALPHA * v.y;
    v.z = (v.z > 0.f) ? v.z : ALPHA * v.z;
    v.w = (v.w > 0.f) ? v.w : ALPHA * v.w;
    ((float4*)out)[i] = v;
}

// ---------------------------------------------------------------------------
extern "C" void kernel_launch(void* const* d_in, const int* in_sizes, int n_in,
                              void* d_out, int out_size) {
    const float* x    = (const float*)d_in[0];
    const void*  ei   = d_in[1];
    const float* W    = (const float*)d_in[2];
    const float* attn = (const float*)d_in[3];
    float*       out  = (float*)d_out;

    const int n_edges = in_sizes[1] / 2;

    // 0: zero accumulators + flag
    {
        const int tot4 = N_NODES * (OUT_DIM / 4);
        zero_kernel<<<(tot4 + 255) / 256, 256>>>();
    }
    // 0b: probe index dtype (treats buffer as int64 candidates)
    probe_kernel<<<16, 256>>>(ei, in_sizes[1]);
    // 1: H = X @ W
    gemm_kernel<<<(N_NODES + 127) / 128, 256>>>(x, W);
    // 2: scores
    score_kernel<<<(N_NODES * 32 + 255) / 256, 256>>>(attn);
    // 3: edge aggregation
    {
        const long long threads = (long long)n_edges * 32;
        edge_kernel<<<(int)((threads + 255) / 256), 256>>>(ei, n_edges);
    }
    // 4: finalize
    {
        const int tot4 = N_NODES * (OUT_DIM / 4);
        finalize_kernel<<<(tot4 + 255) / 256, 256>>>(out);
    }
}

// round 4
// speedup vs baseline: 1.1671x; 1.1671x over previous
#include <cuda_runtime.h>
#include <cuda_bf16.h>
#include <cstdint>

#define N_NODES 100000
#define N_EDGES_MAX 3300000
#define IN_DIM  256
#define OUT_DIM 128
#define ALPHA   0.1f
#define EPS     9e-15f

// ---------------- scratch (device globals; no runtime allocation) ----------
__device__ __align__(16) float g_h[(size_t)N_NODES * OUT_DIM];   // 51.2 MB
__device__ __align__(16) float g_score_l[N_NODES];
__device__ __align__(16) float g_score_r[N_NODES];
__device__ int   g_src[N_EDGES_MAX];
__device__ int   g_dst[N_EDGES_MAX];
__device__ int   g_deg[N_NODES];
__device__ int   g_rowptr[N_NODES];
__device__ int   g_cursor[N_NODES];
__device__ int   g_csr_dst[N_EDGES_MAX];
__device__ float g_csr_w[N_EDGES_MAX];
__device__ int   g_is64;

// ---------------------------------------------------------------------------
// K0: zero degree histogram + reset dtype flag
// ---------------------------------------------------------------------------
__global__ void zero_kernel() {
    int i = blockIdx.x * blockDim.x + threadIdx.x;
    if (i < N_NODES) g_deg[i] = 0;
    if (i == 0) g_is64 = 1;
}

// ---------------------------------------------------------------------------
// K1: probe edge_index dtype (int64 vs int32 delivery)
// ---------------------------------------------------------------------------
__global__ void probe_kernel(const void* ei, int n_elems64) {
    const long long* p = (const long long*)ei;
    int i = threadIdx.x + blockIdx.x * blockDim.x;
    int K = n_elems64 < 4096 ? n_elems64 : 4096;
    if (i < K) {
        long long v = p[i];
        if (v < 0 || v >= N_NODES) atomicAnd(&g_is64, 0);
    }
}

// ---------------------------------------------------------------------------
// K2: convert edge list to int32 arrays + histogram degrees by src
// ---------------------------------------------------------------------------
__global__ __launch_bounds__(256) void convert_hist_kernel(const void* __restrict__ ei_raw,
                                                           const int n_edges) {
    int i = blockIdx.x * blockDim.x + threadIdx.x;
    if (i >= n_edges) return;
    int src, dst;
    if (g_is64) {
        const long long* ei = (const long long*)ei_raw;
        src = (int)ei[i];
        dst = (int)ei[(size_t)n_edges + i];
    } else {
        const int* ei = (const int*)ei_raw;
        src = ei[i];
        dst = ei[(size_t)n_edges + i];
    }
    g_src[i] = src;
    g_dst[i] = dst;
    if ((unsigned)src < N_NODES && (unsigned)dst < N_NODES)
        atomicAdd(&g_deg[src], 1);
}

// ---------------------------------------------------------------------------
// K3: SGEMM  H = X @ W  (128x128 tile, BK=8, double-buffered) + fused scores
// ---------------------------------------------------------------------------
__global__ __launch_bounds__(256) void gemm_score_kernel(const float* __restrict__ X,
                                                         const float* __restrict__ W,
                                                         const float* __restrict__ attn) {
    __shared__ float As[2][8][128];
    __shared__ float Bs[2][8][128];

    const int block_row = blockIdx.x * 128;
    const int tid = threadIdx.x;
    const int ty = tid >> 4;          // 0..15
    const int tx = tid & 15;          // 0..15

    const int arow = tid >> 1;            // 0..127
    const int acol = (tid & 1) * 4;       // 0 or 4
    const int brow = tid >> 5;            // 0..7
    const int bcol = (tid & 31) * 4;      // 0..124

    float acc[8][8];
    #pragma unroll
    for (int i = 0; i < 8; i++)
        #pragma unroll
        for (int j = 0; j < 8; j++) acc[i][j] = 0.f;

    const int gr = block_row + arow;

    // preload tile 0
    float4 av = make_float4(0.f, 0.f, 0.f, 0.f);
    if (gr < N_NODES) av = *(const float4*)(X + (size_t)gr * IN_DIM + acol);
    float4 bv = *(const float4*)(W + (size_t)brow * OUT_DIM + bcol);
    As[0][acol + 0][arow] = av.x;  As[0][acol + 1][arow] = av.y;
    As[0][acol + 2][arow] = av.z;  As[0][acol + 3][arow] = av.w;
    *(float4*)&Bs[0][brow][bcol] = bv;
    __syncthreads();

    int cur = 0;
    for (int kt = 0; kt < IN_DIM; kt += 8) {
        const bool has_next = (kt + 8) < IN_DIM;
        float4 av2, bv2;
        if (has_next) {
            av2 = make_float4(0.f, 0.f, 0.f, 0.f);
            if (gr < N_NODES)
                av2 = *(const float4*)(X + (size_t)gr * IN_DIM + kt + 8 + acol);
            bv2 = *(const float4*)(W + (size_t)(kt + 8 + brow) * OUT_DIM + bcol);
        }

        #pragma unroll
        for (int k = 0; k < 8; k++) {
            float ar[8], br[8];
            *(float4*)&ar[0] = *(float4*)&As[cur][k][ty * 8];
            *(float4*)&ar[4] = *(float4*)&As[cur][k][ty * 8 + 4];
            *(float4*)&br[0] = *(float4*)&Bs[cur][k][tx * 8];
            *(float4*)&br[4] = *(float4*)&Bs[cur][k][tx * 8 + 4];
            #pragma unroll
            for (int i = 0; i < 8; i++)
                #pragma unroll
                for (int j = 0; j < 8; j++)
                    acc[i][j] += ar[i] * br[j];
        }

        if (has_next) {
            const int nb = cur ^ 1;
            As[nb][acol + 0][arow] = av2.x;  As[nb][acol + 1][arow] = av2.y;
            As[nb][acol + 2][arow] = av2.z;  As[nb][acol + 3][arow] = av2.w;
            *(float4*)&Bs[nb][brow][bcol] = bv2;
            __syncthreads();
            cur = nb;
        }
    }

    // store H
    #pragma unroll
    for (int i = 0; i < 8; i++) {
        const int row = block_row + ty * 8 + i;
        if (row < N_NODES) {
            float* hp = g_h + (size_t)row * OUT_DIM + tx * 8;
            *(float4*)(hp)     = *(float4*)&acc[i][0];
            *(float4*)(hp + 4) = *(float4*)&acc[i][4];
        }
    }

    // fused attention scores: reduce partial dots across the 16 tx lanes
    float al[8], ar_[8];
    #pragma unroll
    for (int j = 0; j < 8; j++) {
        al[j]  = attn[tx * 8 + j];
        ar_[j] = attn[OUT_DIM + tx * 8 + j];
    }
    #pragma unroll
    for (int i = 0; i < 8; i++) {
        float dl = 0.f, dr = 0.f;
        #pragma unroll
        for (int j = 0; j < 8; j++) {
            dl += acc[i][j] * al[j];
            dr += acc[i][j] * ar_[j];
        }
        #pragma unroll
        for (int off = 8; off > 0; off >>= 1) {
            dl += __shfl_xor_sync(0xffffffff, dl, off, 16);
            dr += __shfl_xor_sync(0xffffffff, dr, off, 16);
        }
        const int row = block_row + ty * 8 + i;
        if (tx == 0 && row < N_NODES) {
            g_score_l[row] = dl;
            g_score_r[row] = dr;
        }
    }
}

// ---------------------------------------------------------------------------
// K4: exclusive scan of degrees -> rowptr, cursor (single block, 1024 thr)
// ---------------------------------------------------------------------------
__global__ __launch_bounds__(1024) void scan_kernel() {
    __shared__ float _pad[1];        // (unused)
    __shared__ int sh[1024];
    const int t = threadIdx.x;
    const int CHUNK = (N_NODES + 1023) / 1024;   // 98
    const int lo = t * CHUNK;
    const int hi = min(lo + CHUNK, N_NODES);

    int s = 0;
    for (int i = lo; i < hi; i++) s += g_deg[i];
    sh[t] = s;
    __syncthreads();

    // Hillis-Steele inclusive scan over 1024 thread sums
    for (int off = 1; off < 1024; off <<= 1) {
        int v = (t >= off) ? sh[t - off] : 0;
        __syncthreads();
        sh[t] += v;
        __syncthreads();
    }
    int base = sh[t] - s;   // exclusive offset for this thread's chunk

    int run = base;
    for (int i = lo; i < hi; i++) {
        g_rowptr[i] = run;
        g_cursor[i] = run;
        run += g_deg[i];
    }
    (void)_pad;
}

// ---------------------------------------------------------------------------
// K5: scatter edges into CSR with precomputed softmax weights
// ---------------------------------------------------------------------------
__global__ __launch_bounds__(256) void scatter_kernel(const int n_edges) {
    int i = blockIdx.x * blockDim.x + threadIdx.x;
    if (i >= n_edges) return;
    const int src = g_src[i];
    const int dst = g_dst[i];
    if ((unsigned)src >= N_NODES || (unsigned)dst >= N_NODES) return;

    float s = g_score_l[src] + g_score_r[dst];
    s = (s > 0.f) ? s : ALPHA * s;
    const float w = __expf(s);

    const int pos = atomicAdd(&g_cursor[src], 1);
    g_csr_dst[pos] = dst;
    g_csr_w[pos]   = w;
}

// ---------------------------------------------------------------------------
// K6: aggregate per node (one warp per node) + fused finalize -> out
// ---------------------------------------------------------------------------
__global__ __launch_bounds__(256) void aggregate_kernel(float* __restrict__ out) {
    const int node = (blockIdx.x * blockDim.x + threadIdx.x) >> 5;
    const int lane = threadIdx.x & 31;
    if (node >= N_NODES) return;

    const int start = g_rowptr[node];
    const int deg   = g_deg[node];

    float4 acc = make_float4(0.f, 0.f, 0.f, 0.f);
    float wsum = 0.f;

    for (int e = start; e < start + deg; e++) {
        const int   d = g_csr_dst[e];   // broadcast load (same addr all lanes)
        const float w = g_csr_w[e];
        float4 v = *(const float4*)(g_h + (size_t)d * OUT_DIM + lane * 4);
        acc.x += w * v.x; acc.y += w * v.y; acc.z += w * v.z; acc.w += w * v.w;
        wsum  += w;
    }

    const float inv = 1.0f / (wsum + EPS);
    acc.x *= inv; acc.y *= inv; acc.z *= inv; acc.w *= inv;
    acc.x = (acc.x > 0.f) ? acc.x : ALPHA * acc.x;
    acc.y = (acc.y > 0.f) ? acc.y : ALPHA * acc.y;
    acc.z = (acc.z > 0.f) ? acc.z : ALPHA * acc.z;
    acc.w = (acc.w > 0.f) ? acc.w : ALPHA * acc.w;
    *(float4*)(out + (size_t)node * OUT_DIM + lane * 4) = acc;
}

// ---------------------------------------------------------------------------
extern "C" void kernel_launch(void* const* d_in, const int* in_sizes, int n_in,
                              void* d_out, int out_size) {
    const float* x    = (const float*)d_in[0];
    const void*  ei   = d_in[1];
    const float* W    = (const float*)d_in[2];
    const float* attn = (const float*)d_in[3];
    float*       out  = (float*)d_out;

    const int n_edges = in_sizes[1] / 2;

    zero_kernel<<<(N_NODES + 255) / 256, 256>>>();
    probe_kernel<<<16, 256>>>(ei, in_sizes[1]);
    convert_hist_kernel<<<(n_edges + 255) / 256, 256>>>(ei, n_edges);
    gemm_score_kernel<<<(N_NODES + 127) / 128, 256>>>(x, W, attn);
    scan_kernel<<<1, 1024>>>();
    scatter_kernel<<<(n_edges + 255) / 256, 256>>>(n_edges);
    aggregate_kernel<<<(N_NODES * 32 + 255) / 256, 256>>>(out);
}

// round 6
// speedup vs baseline: 1.4124x; 1.2102x over previous
#include <cuda_runtime.h>
#include <cuda_bf16.h>
#include <cstdint>

#define N_NODES 100000
#define N_EDGES_MAX 3300000
#define IN_DIM  256
#define OUT_DIM 128
#define ALPHA   0.1f
#define EPS     9e-15f

// ---------------- scratch (device globals; no runtime allocation) ----------
__device__ __align__(16) float g_h[(size_t)N_NODES * OUT_DIM];   // 51.2 MB
__device__ __align__(16) float g_score_l[N_NODES];
__device__ __align__(16) float g_score_r[N_NODES];
__device__ __align__(16) __nv_bfloat16 g_wt_hi[OUT_DIM * IN_DIM]; // W^T hi  [n][k]
__device__ __align__(16) __nv_bfloat16 g_wt_lo[OUT_DIM * IN_DIM]; // W^T lo
__device__ int   g_src[N_EDGES_MAX];
__device__ int   g_dst[N_EDGES_MAX];
__device__ int   g_deg[N_NODES];
__device__ int   g_rowptr[N_NODES];
__device__ int   g_cursor[N_NODES];
__device__ int   g_csr_dst[N_EDGES_MAX];
__device__ float g_csr_w[N_EDGES_MAX];
__device__ int   g_is64;

__device__ __forceinline__ uint32_t pack2bf16(float x, float y) {
    __nv_bfloat16 hx = __float2bfloat16(x), hy = __float2bfloat16(y);
    uint16_t a = *reinterpret_cast<uint16_t*>(&hx);
    uint16_t b = *reinterpret_cast<uint16_t*>(&hy);
    return (uint32_t)a | ((uint32_t)b << 16);
}

// ---------------------------------------------------------------------------
// K0: zero degree histogram + reset dtype flag
// ---------------------------------------------------------------------------
__global__ void zero_kernel() {
    int i = blockIdx.x * blockDim.x + threadIdx.x;
    if (i < N_NODES) g_deg[i] = 0;
    if (i == 0) g_is64 = 1;
}

// K1: probe dtype (int64 vs int32 delivery)
__global__ void probe_kernel(const void* ei, int n_elems64) {
    const long long* p = (const long long*)ei;
    int i = threadIdx.x + blockIdx.x * blockDim.x;
    int K = n_elems64 < 4096 ? n_elems64 : 4096;
    if (i < K) {
        long long v = p[i];
        if (v < 0 || v >= N_NODES) atomicAnd(&g_is64, 0);
    }
}

// K2: convert edge list + histogram degrees by src
__global__ __launch_bounds__(256) void convert_hist_kernel(const void* __restrict__ ei_raw,
                                                           const int n_edges) {
    int i = blockIdx.x * blockDim.x + threadIdx.x;
    if (i >= n_edges) return;
    int src, dst;
    if (g_is64) {
        const long long* ei = (const long long*)ei_raw;
        src = (int)ei[i];
        dst = (int)ei[(size_t)n_edges + i];
    } else {
        const int* ei = (const int*)ei_raw;
        src = ei[i];
        dst = ei[(size_t)n_edges + i];
    }
    g_src[i] = src;
    g_dst[i] = dst;
    if ((unsigned)src < N_NODES && (unsigned)dst < N_NODES)
        atomicAdd(&g_deg[src], 1);
}

// K3: W^T split into bf16 hi/lo  (Wt[n][k] = W[k][n])
__global__ __launch_bounds__(256) void prep_w_kernel(const float* __restrict__ W) {
    int i = blockIdx.x * blockDim.x + threadIdx.x;
    if (i >= IN_DIM * OUT_DIM) return;
    int n = i % OUT_DIM;
    int k = i / OUT_DIM;
    float w = W[(size_t)k * OUT_DIM + n];
    __nv_bfloat16 hi = __float2bfloat16(w);
    float lo = w - __bfloat162float(hi);
    g_wt_hi[(size_t)n * IN_DIM + k] = hi;
    g_wt_lo[(size_t)n * IN_DIM + k] = __float2bfloat16(lo);
}

// ---------------------------------------------------------------------------
// K4: mma.sync bf16 GEMM  H = X @ W  (3-term bf16 split, fp32 accum)
//   CTA tile 128x128, K in 4 chunks of 64.
//   smem rows padded to 72 bf16 (144 B) -> conflict-free fragment LDS.
//   8 warps as 2(m) x 4(n); warp tile 64x32 = 4 m16-tiles x 4 n8-tiles.
// ---------------------------------------------------------------------------
#define KCHUNK 64
#define ROW_W   72                       // bf16 per padded row
#define TILE_B  (128 * ROW_W * 2)        // 18432 bytes per tile
#define GEMM_SMEM (4 * TILE_B)

__device__ __forceinline__ void mma16816(float* c, const uint32_t* a, const uint32_t* b) {
    asm volatile(
        "mma.sync.aligned.m16n8k16.row.col.f32.bf16.bf16.f32 "
        "{%0,%1,%2,%3}, {%4,%5,%6,%7}, {%8,%9}, {%0,%1,%2,%3};"
        : "+f"(c[0]), "+f"(c[1]), "+f"(c[2]), "+f"(c[3])
        : "r"(a[0]), "r"(a[1]), "r"(a[2]), "r"(a[3]), "r"(b[0]), "r"(b[1]));
}

__global__ __launch_bounds__(256, 2)
void gemm_mma_kernel(const float* __restrict__ X) {
    extern __shared__ __align__(16) char smem_raw[];
    __nv_bfloat16* sAh = (__nv_bfloat16*)(smem_raw);
    __nv_bfloat16* sAl = (__nv_bfloat16*)(smem_raw + TILE_B);
    __nv_bfloat16* sBh = (__nv_bfloat16*)(smem_raw + 2 * TILE_B);
    __nv_bfloat16* sBl = (__nv_bfloat16*)(smem_raw + 3 * TILE_B);

    const int tid  = threadIdx.x;
    const int wid  = tid >> 5;
    const int lane = tid & 31;
    const int g    = lane >> 2;     // 0..7
    const int t    = lane & 3;      // 0..3
    const int wm   = wid >> 2;      // 0..1  (m warp)
    const int wn   = wid & 3;       // 0..3  (n warp)
    const int block_row = blockIdx.x * 128;

    float acc[4][4][4];
    #pragma unroll
    for (int i = 0; i < 4; i++)
        #pragma unroll
        for (int j = 0; j < 4; j++)
            #pragma unroll
            for (int r = 0; r < 4; r++) acc[i][j][r] = 0.f;

    for (int kc = 0; kc < IN_DIM / KCHUNK; kc++) {
        // ---- load + split X chunk (128 rows x 64 cols): 1024 units of 8 cols
        #pragma unroll
        for (int u = 0; u < 4; u++) {
            const int unit = tid + 256 * u;
            const int row  = unit >> 3;
            const int c8   = (unit & 7) * 8;
            const int gr   = block_row + row;
            float4 v0 = make_float4(0.f, 0.f, 0.f, 0.f);
            float4 v1 = make_float4(0.f, 0.f, 0.f, 0.f);
            if (gr < N_NODES) {
                const float* xp = X + (size_t)gr * IN_DIM + kc * KCHUNK + c8;
                v0 = *(const float4*)(xp);
                v1 = *(const float4*)(xp + 4);
            }
            uint4 hi, lo;
            {
                __nv_bfloat16 h0 = __float2bfloat16(v0.x), h1 = __float2bfloat16(v0.y);
                __nv_bfloat16 h2 = __float2bfloat16(v0.z), h3 = __float2bfloat16(v0.w);
                __nv_bfloat16 h4 = __float2bfloat16(v1.x), h5 = __float2bfloat16(v1.y);
                __nv_bfloat16 h6 = __float2bfloat16(v1.z), h7 = __float2bfloat16(v1.w);
                hi.x = ((uint32_t)*(uint16_t*)&h0) | ((uint32_t)*(uint16_t*)&h1 << 16);
                hi.y = ((uint32_t)*(uint16_t*)&h2) | ((uint32_t)*(uint16_t*)&h3 << 16);
                hi.z = ((uint32_t)*(uint16_t*)&h4) | ((uint32_t)*(uint16_t*)&h5 << 16);
                hi.w = ((uint32_t)*(uint16_t*)&h6) | ((uint32_t)*(uint16_t*)&h7 << 16);
                lo.x = pack2bf16(v0.x - __bfloat162float(h0), v0.y - __bfloat162float(h1));
                lo.y = pack2bf16(v0.z - __bfloat162float(h2), v0.w - __bfloat162float(h3));
                lo.z = pack2bf16(v1.x - __bfloat162float(h4), v1.y - __bfloat162float(h5));
                lo.w = pack2bf16(v1.z - __bfloat162float(h6), v1.w - __bfloat162float(h7));
            }
            *(uint4*)(sAh + row * ROW_W + c8) = hi;
            *(uint4*)(sAl + row * ROW_W + c8) = lo;
        }
        // ---- load B chunk (Wt hi/lo, 128 n-rows x 64 k)
        #pragma unroll
        for (int u = 0; u < 4; u++) {
            const int unit = tid + 256 * u;
            const int n    = unit >> 3;
            const int c8   = (unit & 7) * 8;
            const size_t gofs = (size_t)n * IN_DIM + kc * KCHUNK + c8;
            *(uint4*)(sBh + n * ROW_W + c8) = *(const uint4*)(g_wt_hi + gofs);
            *(uint4*)(sBl + n * ROW_W + c8) = *(const uint4*)(g_wt_lo + gofs);
        }
        __syncthreads();

        const uint32_t* Ah = (const uint32_t*)sAh;
        const uint32_t* Al = (const uint32_t*)sAl;
        const uint32_t* Bh = (const uint32_t*)sBh;
        const uint32_t* Bl = (const uint32_t*)sBl;
        const int RW = ROW_W / 2;   // 36 words per row

        #define DO_TERM(Ap, Bp)                                                        \
        {                                                                              \
            _Pragma("unroll")                                                          \
            for (int ks = 0; ks < 4; ks++) {                                           \
                uint32_t afr[4][4];                                                    \
                _Pragma("unroll")                                                      \
                for (int mt = 0; mt < 4; mt++) {                                       \
                    const int row = wm * 64 + mt * 16 + g;                             \
                    afr[mt][0] = Ap[row * RW + ks * 8 + t];                            \
                    afr[mt][1] = Ap[(row + 8) * RW + ks * 8 + t];                      \
                    afr[mt][2] = Ap[row * RW + ks * 8 + t + 4];                        \
                    afr[mt][3] = Ap[(row + 8) * RW + ks * 8 + t + 4];                  \
                }                                                                      \
                uint32_t bfr[4][2];                                                    \
                _Pragma("unroll")                                                      \
                for (int nt = 0; nt < 4; nt++) {                                       \
                    const int nr = wn * 32 + nt * 8 + g;                               \
                    bfr[nt][0] = Bp[nr * RW + ks * 8 + t];                             \
                    bfr[nt][1] = Bp[nr * RW + ks * 8 + t + 4];                         \
                }                                                                      \
                _Pragma("unroll")                                                      \
                for (int mt = 0; mt < 4; mt++)                                         \
                    _Pragma("unroll")                                                  \
                    for (int nt = 0; nt < 4; nt++)                                     \
                        mma16816(acc[mt][nt], afr[mt], bfr[nt]);                       \
            }                                                                          \
        }

        DO_TERM(Ah, Bh);
        DO_TERM(Ah, Bl);
        DO_TERM(Al, Bh);
        #undef DO_TERM
        __syncthreads();
    }

    // ---- epilogue: write H
    #pragma unroll
    for (int mt = 0; mt < 4; mt++) {
        const int r0 = block_row + wm * 64 + mt * 16 + g;
        const int r1 = r0 + 8;
        #pragma unroll
        for (int nt = 0; nt < 4; nt++) {
            const int col = wn * 32 + nt * 8 + 2 * t;
            if (r0 < N_NODES)
                *(float2*)(g_h + (size_t)r0 * OUT_DIM + col) = make_float2(acc[mt][nt][0], acc[mt][nt][1]);
            if (r1 < N_NODES)
                *(float2*)(g_h + (size_t)r1 * OUT_DIM + col) = make_float2(acc[mt][nt][2], acc[mt][nt][3]);
        }
    }
}

// ---------------------------------------------------------------------------
// K5: per-node attention scores  (one warp per node)
// ---------------------------------------------------------------------------
__global__ __launch_bounds__(256) void score_kernel(const float* __restrict__ attn) {
    const int warp = (blockIdx.x * blockDim.x + threadIdx.x) >> 5;
    const int lane = threadIdx.x & 31;
    if (warp >= N_NODES) return;

    float4 hv = *(const float4*)(g_h + (size_t)warp * OUT_DIM + lane * 4);
    float4 al = *(const float4*)(attn + lane * 4);
    float4 ar = *(const float4*)(attn + OUT_DIM + lane * 4);

    float dl = hv.x * al.x + hv.y * al.y + hv.z * al.z + hv.w * al.w;
    float dr = hv.x * ar.x + hv.y * ar.y + hv.z * ar.z + hv.w * ar.w;

    #pragma unroll
    for (int off = 16; off > 0; off >>= 1) {
        dl += __shfl_xor_sync(0xffffffff, dl, off);
        dr += __shfl_xor_sync(0xffffffff, dr, off);
    }
    if (lane == 0) {
        g_score_l[warp] = dl;
        g_score_r[warp] = dr;
    }
}

// ---------------------------------------------------------------------------
// K6: exclusive scan of degrees -> rowptr, cursor
// ---------------------------------------------------------------------------
__global__ __launch_bounds__(1024) void scan_kernel() {
    __shared__ int sh[1024];
    const int t = threadIdx.x;
    const int CHUNK = (N_NODES + 1023) / 1024;
    const int lo = t * CHUNK;
    const int hi = min(lo + CHUNK, N_NODES);

    int s = 0;
    for (int i = lo; i < hi; i++) s += g_deg[i];
    sh[t] = s;
    __syncthreads();
    for (int off = 1; off < 1024; off <<= 1) {
        int v = (t >= off) ? sh[t - off] : 0;
        __syncthreads();
        sh[t] += v;
        __syncthreads();
    }
    int run = sh[t] - s;
    for (int i = lo; i < hi; i++) {
        g_rowptr[i] = run;
        g_cursor[i] = run;
        run += g_deg[i];
    }
}

// ---------------------------------------------------------------------------
// K7: scatter edges into CSR with precomputed softmax weights
// ---------------------------------------------------------------------------
__global__ __launch_bounds__(256) void scatter_kernel(const int n_edges) {
    int i = blockIdx.x * blockDim.x + threadIdx.x;
    if (i >= n_edges) return;
    const int src = g_src[i];
    const int dst = g_dst[i];
    if ((unsigned)src >= N_NODES || (unsigned)dst >= N_NODES) return;

    float s = g_score_l[src] + g_score_r[dst];
    s = (s > 0.f) ? s : ALPHA * s;
    const float w = __expf(s);

    const int pos = atomicAdd(&g_cursor[src], 1);
    g_csr_dst[pos] = dst;
    g_csr_w[pos]   = w;
}

// ---------------------------------------------------------------------------
// K8: aggregate per node (one warp per node, 4-wide unrolled gather)
// ---------------------------------------------------------------------------
__global__ __launch_bounds__(256) void aggregate_kernel(float* __restrict__ out) {
    const int node = (blockIdx.x * blockDim.x + threadIdx.x) >> 5;
    const int lane = threadIdx.x & 31;
    if (node >= N_NODES) return;

    const int start = g_rowptr[node];
    const int deg   = g_deg[node];
    const int end   = start + deg;

    float4 acc = make_float4(0.f, 0.f, 0.f, 0.f);
    float wsum = 0.f;

    int e = start;
    for (; e + 4 <= end; e += 4) {
        int d0 = g_csr_dst[e], d1 = g_csr_dst[e + 1], d2 = g_csr_dst[e + 2], d3 = g_csr_dst[e + 3];
        float w0 = g_csr_w[e], w1 = g_csr_w[e + 1], w2 = g_csr_w[e + 2], w3 = g_csr_w[e + 3];
        float4 v0 = *(const float4*)(g_h + (size_t)d0 * OUT_DIM + lane * 4);
        float4 v1 = *(const float4*)(g_h + (size_t)d1 * OUT_DIM + lane * 4);
        float4 v2 = *(const float4*)(g_h + (size_t)d2 * OUT_DIM + lane * 4);
        float4 v3 = *(const float4*)(g_h + (size_t)d3 * OUT_DIM + lane * 4);
        acc.x += w0 * v0.x + w1 * v1.x + w2 * v2.x + w3 * v3.x;
        acc.y += w0 * v0.y + w1 * v1.y + w2 * v2.y + w3 * v3.y;
        acc.z += w0 * v0.z + w1 * v1.z + w2 * v2.z + w3 * v3.z;
        acc.w += w0 * v0.w + w1 * v1.w + w2 * v2.w + w3 * v3.w;
        wsum  += w0 + w1 + w2 + w3;
    }
    for (; e < end; e++) {
        const int   d = g_csr_dst[e];
        const float w = g_csr_w[e];
        float4 v = *(const float4*)(g_h + (size_t)d * OUT_DIM + lane * 4);
        acc.x += w * v.x; acc.y += w * v.y; acc.z += w * v.z; acc.w += w * v.w;
        wsum  += w;
    }

    const float inv = 1.0f / (wsum + EPS);
    acc.x *= inv; acc.y *= inv; acc.z *= inv; acc.w *= inv;
    acc.x = (acc.x > 0.f) ? acc.x : ALPHA * acc.x;
    acc.y = (acc.y > 0.f) ? acc.y : ALPHA * acc.y;
    acc.z = (acc.z > 0.f) ? acc.z : ALPHA * acc.z;
    acc.w = (acc.w > 0.f) ? acc.w : ALPHA * acc.w;
    *(float4*)(out + (size_t)node * OUT_DIM + lane * 4) = acc;
}

// ---------------------------------------------------------------------------
extern "C" void kernel_launch(void* const* d_in, const int* in_sizes, int n_in,
                              void* d_out, int out_size) {
    const float* x    = (const float*)d_in[0];
    const void*  ei   = d_in[1];
    const float* W    = (const float*)d_in[2];
    const float* attn = (const float*)d_in[3];
    float*       out  = (float*)d_out;

    const int n_edges = in_sizes[1] / 2;

    cudaFuncSetAttribute(gemm_mma_kernel, cudaFuncAttributeMaxDynamicSharedMemorySize, GEMM_SMEM);

    zero_kernel<<<(N_NODES + 255) / 256, 256>>>();
    probe_kernel<<<16, 256>>>(ei, in_sizes[1]);
    convert_hist_kernel<<<(n_edges + 255) / 256, 256>>>(ei, n_edges);
    prep_w_kernel<<<(IN_DIM * OUT_DIM + 255) / 256, 256>>>(W);
    gemm_mma_kernel<<<(N_NODES + 127) / 128, 256, GEMM_SMEM>>>(x);
    score_kernel<<<(N_NODES * 32 + 255) / 256, 256>>>(attn);
    scan_kernel<<<1, 1024>>>();
    scatter_kernel<<<(n_edges + 255) / 256, 256>>>(n_edges);
    aggregate_kernel<<<(N_NODES * 32 + 255) / 256, 256>>>(out);
}